// round 1
// baseline (speedup 1.0000x reference)
#include <cuda_runtime.h>
#include <stdint.h>
#include <math.h>

// DistanceTransformLoss: out = mean(BCEWithLogits(pred, tgt))
//                            + sqrt( sum(pred_bin * dist) / max(count,1) )  [0 if sum==0]
// dist[h] = min(|h - nearest target in column (along H)|, H), per (n, w) column.
//
// Shapes: (N=32, C=1, H=1024, W=1024) fp32.
// Strategy: 1 streaming pass over HBM (targets+preds read once, coalesced),
// caching per-column target/pred bitmasks in SMEM; pass 2 computes the
// border term purely from the cached bits with a set-bit iterator.

#define NTHREADS 128
#define NBLOCKS  256          // 32 n * (1024/128) w-tiles
#define HH 1024
#define WW 1024
#define NWORDS 32             // 1024 bits / 32

__device__ double       g_part_bce[NBLOCKS];
__device__ unsigned int g_part_tot[NBLOCKS];
__device__ unsigned int g_part_cnt[NBLOCKS];

__global__ void __launch_bounds__(NTHREADS)
dtl_main(const float* __restrict__ preds, const float* __restrict__ targs) {
    __shared__ uint32_t s_t[NWORDS * NTHREADS];
    __shared__ uint32_t s_p[NWORDS * NTHREADS];

    const int tid = threadIdx.x;
    const int n   = blockIdx.x >> 3;          // 8 w-tiles per n
    const int w0  = (blockIdx.x & 7) << 7;    // * 128
    const int col = w0 + tid;
    int idx = n * (HH * WW) + col;

    float bce = 0.f;

    // ---- Pass 1: stream column, accumulate BCE, pack bits ----
    for (int word = 0; word < NWORDS; ++word) {
        uint32_t tw = 0u, pw = 0u;
        #pragma unroll
        for (int bb = 0; bb < 32; bb += 8) {
            float pv[8], tv[8];
            #pragma unroll
            for (int j = 0; j < 8; ++j) {
                pv[j] = preds[idx + j * WW];
                tv[j] = targs[idx + j * WW];
            }
            idx += 8 * WW;
            #pragma unroll
            for (int j = 0; j < 8; ++j) {
                float p = pv[j], t = tv[j];
                float a = fabsf(p);
                // max(p,0) - p*t + log1p(exp(-|p|)); __logf abs-err near 1 is ~1e-7, fine.
                bce += fmaxf(p, 0.f) - p * t + __logf(1.f + __expf(-a));
                if (t > 0.5f) tw |= (1u << (bb + j));
                if (p > 0.0f) pw |= (1u << (bb + j));   // sigmoid(p) > 0.5  <=>  p > 0
            }
        }
        s_t[word * NTHREADS + tid] = tw;
        s_p[word * NTHREADS + tid] = pw;
    }
    // each thread only reads its own column's bits -> no __syncthreads needed

    // ---- Pass 2: border term from cached bits ----
    const uint32_t* stc = s_t + tid;
    const uint32_t* spc = s_p + tid;

    // set-bit iterator over target positions (increasing h)
    int scanw = 0;
    uint32_t curm = stc[0];
    int nt;  // smallest unconsumed target position >= current h (or BIG)
    {
        while (curm == 0u && scanw < NWORDS - 1) { ++scanw; curm = stc[scanw * NTHREADS]; }
        if (curm) { nt = (scanw << 5) + __ffs(curm) - 1; curm &= curm - 1u; }
        else        nt = 1 << 20;
    }

    int lt = -(1 << 20);  // last target position <= h (or -BIG)
    uint32_t tot = 0u, cnt = 0u;

    for (int word = 0; word < NWORDS; ++word) {
        uint32_t tw = stc[word * NTHREADS];
        uint32_t pw = spc[word * NTHREADS];
        int hbase = word << 5;
        #pragma unroll 4
        for (int b = 0; b < 32; ++b) {
            int h = hbase + b;
            if ((tw >> b) & 1u) {
                lt = h;                      // dist=0 here -> no contribution
                // advance iterator past h (nt == h by invariant)
                while (curm == 0u && scanw < NWORDS - 1) { ++scanw; curm = stc[scanw * NTHREADS]; }
                if (curm) { nt = (scanw << 5) + __ffs(curm) - 1; curm &= curm - 1u; }
                else        nt = 1 << 20;
            } else if ((pw >> b) & 1u) {
                int dist = min(min(h - lt, nt - h), HH);
                tot += (uint32_t)dist;       // dist >= 1 here (not at a target)
                cnt += 1u;
            }
        }
    }

    // ---- Block reduction -> fixed per-block slots (deterministic) ----
    const unsigned fullm = 0xFFFFFFFFu;
    for (int off = 16; off; off >>= 1) {
        bce += __shfl_down_sync(fullm, bce, off);
        tot += __shfl_down_sync(fullm, tot, off);
        cnt += __shfl_down_sync(fullm, cnt, off);
    }
    __shared__ float    rb[4];
    __shared__ uint32_t rt[4], rc[4];
    int wid = tid >> 5, lane = tid & 31;
    if (lane == 0) { rb[wid] = bce; rt[wid] = tot; rc[wid] = cnt; }
    __syncthreads();
    if (tid == 0) {
        g_part_bce[blockIdx.x] = (double)(rb[0] + rb[1] + rb[2] + rb[3]);
        g_part_tot[blockIdx.x] = rt[0] + rt[1] + rt[2] + rt[3];
        g_part_cnt[blockIdx.x] = rc[0] + rc[1] + rc[2] + rc[3];
    }
}

__global__ void dtl_final(float* __restrict__ out) {
    __shared__ double             sb[NBLOCKS];
    __shared__ unsigned long long st[NBLOCKS], sc[NBLOCKS];
    int tid = threadIdx.x;
    sb[tid] = g_part_bce[tid];
    st[tid] = (unsigned long long)g_part_tot[tid];
    sc[tid] = (unsigned long long)g_part_cnt[tid];
    __syncthreads();
    for (int s = NBLOCKS / 2; s; s >>= 1) {
        if (tid < s) { sb[tid] += sb[tid + s]; st[tid] += st[tid + s]; sc[tid] += sc[tid + s]; }
        __syncthreads();
    }
    if (tid == 0) {
        double bce_mean = sb[0] / 33554432.0;  // 32*1*1024*1024
        double tot = (double)st[0];
        double cnt = (double)sc[0];
        double border = (st[0] == 0ull) ? 0.0 : tot / (cnt < 1.0 ? 1.0 : cnt);
        out[0] = (float)(bce_mean + sqrt(border));
    }
}

extern "C" void kernel_launch(void* const* d_in, const int* in_sizes, int n_in,
                              void* d_out, int out_size) {
    const float* preds = (const float*)d_in[0];
    const float* targs = (const float*)d_in[1];
    dtl_main<<<NBLOCKS, NTHREADS>>>(preds, targs);
    dtl_final<<<1, NBLOCKS>>>((float*)d_out);
}

// round 4
// speedup vs baseline: 1.7141x; 1.7141x over previous
#include <cuda_runtime.h>
#include <stdint.h>
#include <math.h>

// DistanceTransformLoss: out = mean(BCEWithLogits(pred, tgt))
//                            + sqrt( sum(pred_bin*dist) / max(count,1) )  [0 if sum==0]
// dist[h] = min(|h - nearest target along H in column|, H) per (n,w) column.
// Shapes: (32,1,1024,1024) fp32.
//
// Block = 32 columns x full H. 256 threads: warp g (0..7) streams rows
// [128g,128g+128) for lanes' 32 columns (coalesced 128B loads), accumulates
// BCE, packs target/pred-sign bits into SMEM. After one sync, each thread
// resolves the distance transform for its own 128-bit segment using the
// column's full 1024-bit mask in SMEM.

#define NTHREADS 256
#define NBLOCKS  1024          // 32 n * (1024/32) w-tiles
#define HH 1024
#define WW 1024
#define NWORDS 32              // 1024 bits / 32
#define TILE_W 32
#define BIG (1 << 20)

__device__ double       g_part_bce[NBLOCKS];
__device__ unsigned int g_part_tot[NBLOCKS];
__device__ unsigned int g_part_cnt[NBLOCKS];

__global__ void __launch_bounds__(NTHREADS, 6)
dtl_main(const float* __restrict__ preds, const float* __restrict__ targs) {
    __shared__ uint32_t s_t[NWORDS * TILE_W];
    __shared__ uint32_t s_p[NWORDS * TILE_W];

    const int tid  = threadIdx.x;
    const int g    = tid >> 5;              // warp id = row segment 0..7
    const int lane = tid & 31;              // column within tile
    const int n    = blockIdx.x >> 5;       // 32 tiles per n
    const int w0   = (blockIdx.x & 31) << 5;

    int idx = n * (HH * WW) + (g << 7) * WW + w0 + lane;

    float bce = 0.f;

    // ---- Pass 1: stream 128 rows, accumulate BCE, pack 4 bit-words ----
    #pragma unroll
    for (int w4 = 0; w4 < 4; ++w4) {
        uint32_t tw = 0u, pw = 0u;
        #pragma unroll
        for (int bb = 0; bb < 32; bb += 8) {
            float pv[8], tv[8];
            #pragma unroll
            for (int j = 0; j < 8; ++j) {
                pv[j] = __ldcs(preds + idx + j * WW);
                tv[j] = __ldcs(targs + idx + j * WW);
            }
            idx += 8 * WW;
            #pragma unroll
            for (int j = 0; j < 8; ++j) {
                float p = pv[j], t = tv[j];
                bce += fmaxf(p, 0.f) - p * t + __logf(1.f + __expf(-fabsf(p)));
                if (t > 0.5f) tw |= (1u << (bb + j));
                if (p > 0.0f) pw |= (1u << (bb + j));  // sigmoid(p)>0.5 <=> p>0
            }
        }
        s_t[((g << 2) + w4) * TILE_W + lane] = tw;
        s_p[((g << 2) + w4) * TILE_W + lane] = pw;
    }
    __syncthreads();

    // ---- Pass 2: per-thread 128-bit segment of the distance transform ----
    const uint32_t* stc = s_t + lane;
    const uint32_t* spc = s_p + lane;
    const int w4base = g << 2;

    // lt: last target position before segment start
    int lt = -BIG;
    for (int w = w4base - 1; w >= 0; --w) {
        uint32_t v = stc[w * TILE_W];
        if (v) { lt = (w << 5) + 31 - __clz(v); break; }
    }
    // nt iterator: next target position >= segment start
    int scanw = w4base;
    uint32_t curm = stc[scanw * TILE_W];
    int nt;
    while (curm == 0u && scanw < NWORDS - 1) { ++scanw; curm = stc[scanw * TILE_W]; }
    if (curm) { nt = (scanw << 5) + __ffs(curm) - 1; curm &= curm - 1u; }
    else        nt = BIG;

    uint32_t tot = 0u, cnt = 0u;
    #pragma unroll
    for (int w4 = 0; w4 < 4; ++w4) {
        uint32_t tw = stc[(w4base + w4) * TILE_W];
        uint32_t pw = spc[(w4base + w4) * TILE_W];
        int hbase = (w4base + w4) << 5;
        #pragma unroll 4
        for (int b = 0; b < 32; ++b) {
            int h = hbase + b;
            if ((tw >> b) & 1u) {
                lt = h;
                while (curm == 0u && scanw < NWORDS - 1) { ++scanw; curm = stc[scanw * TILE_W]; }
                if (curm) { nt = (scanw << 5) + __ffs(curm) - 1; curm &= curm - 1u; }
                else        nt = BIG;
            } else if ((pw >> b) & 1u) {
                tot += (uint32_t)min(min(h - lt, nt - h), HH);
                cnt += 1u;
            }
        }
    }

    // ---- Block reduction -> fixed per-block slots (deterministic) ----
    const unsigned fullm = 0xFFFFFFFFu;
    for (int off = 16; off; off >>= 1) {
        bce += __shfl_down_sync(fullm, bce, off);
        tot += __shfl_down_sync(fullm, tot, off);
        cnt += __shfl_down_sync(fullm, cnt, off);
    }
    __shared__ float    rb[8];
    __shared__ uint32_t rt[8], rc[8];
    if (lane == 0) { rb[g] = bce; rt[g] = tot; rc[g] = cnt; }
    __syncthreads();
    if (tid == 0) {
        float    b2 = 0.f;
        uint32_t t2 = 0u, c2 = 0u;
        #pragma unroll
        for (int i = 0; i < 8; ++i) { b2 += rb[i]; t2 += rt[i]; c2 += rc[i]; }
        g_part_bce[blockIdx.x] = (double)b2;
        g_part_tot[blockIdx.x] = t2;
        g_part_cnt[blockIdx.x] = c2;
    }
}

// 256 threads; each folds 4 partials on load (1024 slots total).
__global__ void __launch_bounds__(256) dtl_final(float* __restrict__ out) {
    __shared__ double             sb[256];
    __shared__ unsigned long long st[256], sc[256];
    int tid = threadIdx.x;
    double             b = 0.0;
    unsigned long long t = 0ull, c = 0ull;
    #pragma unroll
    for (int i = 0; i < 4; ++i) {
        int k = tid + 256 * i;
        b += g_part_bce[k];
        t += (unsigned long long)g_part_tot[k];
        c += (unsigned long long)g_part_cnt[k];
    }
    sb[tid] = b; st[tid] = t; sc[tid] = c;
    __syncthreads();
    for (int s = 128; s; s >>= 1) {
        if (tid < s) { sb[tid] += sb[tid + s]; st[tid] += st[tid + s]; sc[tid] += sc[tid + s]; }
        __syncthreads();
    }
    if (tid == 0) {
        double bce_mean = sb[0] / 33554432.0;  // 32*1024*1024
        double tot = (double)st[0];
        double cnt = (double)sc[0];
        double border = (st[0] == 0ull) ? 0.0 : tot / (cnt < 1.0 ? 1.0 : cnt);
        out[0] = (float)(bce_mean + sqrt(border));
    }
}

extern "C" void kernel_launch(void* const* d_in, const int* in_sizes, int n_in,
                              void* d_out, int out_size) {
    const float* preds = (const float*)d_in[0];
    const float* targs = (const float*)d_in[1];
    dtl_main<<<NBLOCKS, NTHREADS>>>(preds, targs);
    dtl_final<<<1, 256>>>((float*)d_out);
}